// round 1
// baseline (speedup 1.0000x reference)
#include <cuda_runtime.h>

#define TT   128
#define BLK  128

// ---- shared layout (floats) ----
// per-LSTM block: WihT[5][20] (100) + WhhT[5][20] (100) + Bsum[20] = 220
#define L1_OFF 0
#define L2_OFF 220
#define L3_OFF 440
#define FC_OFF 660
#define FW1 (FC_OFF)
#define FB1 (FW1+640)
#define FW2 (FB1+32)
#define FB2 (FW2+1024)
#define FW3 (FB2+32)
#define FB3 (FW3+512)
#define FW4 (FB3+16)
#define FB4 (FW4+256)
#define FW5 (FB4+16)
#define FB5 (FW5+80)
#define S_TOTAL (FB5+5)   // 3273 floats = ~13.1 KB

__device__ __forceinline__ float sigm(float x) {
    return 1.0f / (1.0f + __expf(-x));
}
__device__ __forceinline__ float tanh_(float x) {
    // tanh(x) = 2*sigmoid(2x) - 1   (2 MUFU, accurate ~1e-7 rel)
    return 2.0f / (1.0f + __expf(-2.0f * x)) - 1.0f;
}

// One LSTM cell step. Weights transposed in shared: WT[k*20 + j], 16B-aligned rows.
__device__ __forceinline__ void lstm_step(const float* __restrict__ sWT,
                                          const float* __restrict__ sUT,
                                          const float* __restrict__ sB,
                                          const float* __restrict__ x,
                                          float* __restrict__ h,
                                          float* __restrict__ c) {
    float g[20];
    {
        const float4* b4 = reinterpret_cast<const float4*>(sB);
        #pragma unroll
        for (int q = 0; q < 5; q++) {
            float4 v = b4[q];
            g[4*q+0] = v.x; g[4*q+1] = v.y; g[4*q+2] = v.z; g[4*q+3] = v.w;
        }
    }
    #pragma unroll
    for (int k = 0; k < 5; k++) {
        float xk = x[k];
        const float4* w4 = reinterpret_cast<const float4*>(sWT + k * 20);
        #pragma unroll
        for (int q = 0; q < 5; q++) {
            float4 w = w4[q];
            g[4*q+0] += w.x * xk; g[4*q+1] += w.y * xk;
            g[4*q+2] += w.z * xk; g[4*q+3] += w.w * xk;
        }
    }
    #pragma unroll
    for (int k = 0; k < 5; k++) {
        float hk = h[k];
        const float4* w4 = reinterpret_cast<const float4*>(sUT + k * 20);
        #pragma unroll
        for (int q = 0; q < 5; q++) {
            float4 w = w4[q];
            g[4*q+0] += w.x * hk; g[4*q+1] += w.y * hk;
            g[4*q+2] += w.z * hk; g[4*q+3] += w.w * hk;
        }
    }
    #pragma unroll
    for (int m = 0; m < 5; m++) {
        float ig = sigm(g[m]);
        float fg = sigm(g[5 + m]);
        float gg = tanh_(g[10 + m]);
        float og = sigm(g[15 + m]);
        float cm = fg * c[m] + ig * gg;
        c[m] = cm;
        h[m] = og * tanh_(cm);
    }
}

struct Params {
    const float *x1, *x2;
    const float *Wih1, *Whh1, *bih1, *bhh1;
    const float *Wih2a, *Whh2a, *bih2a, *bhh2a;
    const float *Wih2b, *Whh2b, *bih2b, *bhh2b;
    const float *W1, *b1, *W2, *b2, *W3, *b3, *W4, *b4, *W5, *b5;
    float* out;
    int B;
};

__global__ __launch_bounds__(BLK)
void dynrnn_kernel(Params p) {
    __shared__ float s[S_TOTAL];
    const int tid = threadIdx.x;

    // ---- cooperative weight staging ----
    // transposed LSTM weight copies: s[off + k*20 + j] = W[j*5 + k]
    {
        const float* srcs[6] = { p.Wih1, p.Whh1, p.Wih2a, p.Whh2a, p.Wih2b, p.Whh2b };
        const int    offs[6] = { L1_OFF, L1_OFF+100, L2_OFF, L2_OFF+100, L3_OFF, L3_OFF+100 };
        for (int m = 0; m < 6; m++) {
            const float* W = srcs[m];
            int off = offs[m];
            for (int i = tid; i < 100; i += BLK) {
                int j = i / 5, k = i % 5;
                s[off + k * 20 + j] = W[i];
            }
        }
        for (int i = tid; i < 20; i += BLK) {
            s[L1_OFF + 200 + i] = p.bih1[i]  + p.bhh1[i];
            s[L2_OFF + 200 + i] = p.bih2a[i] + p.bhh2a[i];
            s[L3_OFF + 200 + i] = p.bih2b[i] + p.bhh2b[i];
        }
        for (int i = tid; i < 640;  i += BLK) s[FW1 + i] = p.W1[i];
        for (int i = tid; i < 32;   i += BLK) s[FB1 + i] = p.b1[i];
        for (int i = tid; i < 1024; i += BLK) s[FW2 + i] = p.W2[i];
        for (int i = tid; i < 32;   i += BLK) s[FB2 + i] = p.b2[i];
        for (int i = tid; i < 512;  i += BLK) s[FW3 + i] = p.W3[i];
        for (int i = tid; i < 16;   i += BLK) s[FB3 + i] = p.b3[i];
        for (int i = tid; i < 256;  i += BLK) s[FW4 + i] = p.W4[i];
        for (int i = tid; i < 16;   i += BLK) s[FB4 + i] = p.b4[i];
        for (int i = tid; i < 80;   i += BLK) s[FW5 + i] = p.W5[i];
        for (int i = tid; i < 5;    i += BLK) s[FB5 + i] = p.b5[i];
    }
    __syncthreads();

    const int b = blockIdx.x * BLK + tid;
    if (b >= p.B) return;

    const float* __restrict__ x1p = p.x1 + (size_t)b * TT * 5;
    const float* __restrict__ x2p = p.x2 + (size_t)b * TT * 5;

    float h1[5], c1[5], h2a[5], c2a[5], h2b[5], c2b[5];
    #pragma unroll
    for (int m = 0; m < 5; m++) {
        h1[m] = c1[m] = h2a[m] = c2a[m] = h2b[m] = c2b[m] = 0.0f;
    }

    float xa[5], xb[5];
    #pragma unroll
    for (int j = 0; j < 5; j++) {
        xa[j] = __ldg(x1p + j);
        xb[j] = __ldg(x2p + j);
    }

    #pragma unroll 1
    for (int t = 0; t < TT; t++) {
        // prefetch next timestep (re-loads t=127 on last iter; harmless & keeps xa = x[127])
        float nxa[5], nxb[5];
        int tn = (t + 1 < TT) ? (t + 1) : t;
        #pragma unroll
        for (int j = 0; j < 5; j++) {
            nxa[j] = __ldg(x1p + tn * 5 + j);
            nxb[j] = __ldg(x2p + tn * 5 + j);
        }

        lstm_step(&s[L1_OFF], &s[L1_OFF + 100], &s[L1_OFF + 200], xa,  h1,  c1);
        lstm_step(&s[L2_OFF], &s[L2_OFF + 100], &s[L2_OFF + 200], xb,  h2a, c2a);
        lstm_step(&s[L3_OFF], &s[L3_OFF + 100], &s[L3_OFF + 200], h2a, h2b, c2b);

        #pragma unroll
        for (int j = 0; j < 5; j++) { xa[j] = nxa[j]; xb[j] = nxb[j]; }
    }

    // ---- FC head: concat [x1_last, x2_last, out1, out2] -> 20 ----
    float a0[20];
    #pragma unroll
    for (int j = 0; j < 5; j++) {
        a0[j]      = xa[j];
        a0[5 + j]  = xb[j];
        a0[10 + j] = h1[j];
        a0[15 + j] = h2b[j];
    }
    float a1[32];
    #pragma unroll
    for (int j = 0; j < 32; j++) {
        float acc = s[FB1 + j];
        #pragma unroll
        for (int k = 0; k < 20; k++) acc += s[FW1 + j * 20 + k] * a0[k];
        a1[j] = fmaxf(acc, 0.0f);
    }
    float a2[32];
    #pragma unroll
    for (int j = 0; j < 32; j++) {
        float acc = s[FB2 + j];
        #pragma unroll
        for (int k = 0; k < 32; k++) acc += s[FW2 + j * 32 + k] * a1[k];
        a2[j] = fmaxf(acc, 0.0f);
    }
    float a3[16];
    #pragma unroll
    for (int j = 0; j < 16; j++) {
        float acc = s[FB3 + j];
        #pragma unroll
        for (int k = 0; k < 32; k++) acc += s[FW3 + j * 32 + k] * a2[k];
        a3[j] = fmaxf(acc, 0.0f);
    }
    float a4[16];
    #pragma unroll
    for (int j = 0; j < 16; j++) {
        float acc = s[FB4 + j];
        #pragma unroll
        for (int k = 0; k < 16; k++) acc += s[FW4 + j * 16 + k] * a3[k];
        a4[j] = fmaxf(acc, 0.0f);
    }
    #pragma unroll
    for (int j = 0; j < 5; j++) {
        float acc = s[FB5 + j];
        #pragma unroll
        for (int k = 0; k < 16; k++) acc += s[FW5 + j * 16 + k] * a4[k];
        p.out[(size_t)b * 5 + j] = acc;
    }
}

extern "C" void kernel_launch(void* const* d_in, const int* in_sizes, int n_in,
                              void* d_out, int out_size) {
    Params p;
    p.x1    = (const float*)d_in[0];
    p.x2    = (const float*)d_in[1];
    p.Wih1  = (const float*)d_in[2];
    p.Whh1  = (const float*)d_in[3];
    p.bih1  = (const float*)d_in[4];
    p.bhh1  = (const float*)d_in[5];
    p.Wih2a = (const float*)d_in[6];
    p.Whh2a = (const float*)d_in[7];
    p.bih2a = (const float*)d_in[8];
    p.bhh2a = (const float*)d_in[9];
    p.Wih2b = (const float*)d_in[10];
    p.Whh2b = (const float*)d_in[11];
    p.bih2b = (const float*)d_in[12];
    p.bhh2b = (const float*)d_in[13];
    p.W1 = (const float*)d_in[14];  p.b1 = (const float*)d_in[15];
    p.W2 = (const float*)d_in[16];  p.b2 = (const float*)d_in[17];
    p.W3 = (const float*)d_in[18];  p.b3 = (const float*)d_in[19];
    p.W4 = (const float*)d_in[20];  p.b4 = (const float*)d_in[21];
    p.W5 = (const float*)d_in[22];  p.b5 = (const float*)d_in[23];
    p.out = (float*)d_out;
    p.B   = in_sizes[0] / (TT * 5);

    int grid = (p.B + BLK - 1) / BLK;
    dynrnn_kernel<<<grid, BLK>>>(p);
}